// round 16
// baseline (speedup 1.0000x reference)
#include <cuda_runtime.h>
#include <cstdint>

#define NN 50000
#define EE 800000

// ---------------- scratch (static device globals; no allocation) ----------------
__device__ float g_buf0[NN * 256];
__device__ float g_buf1[NN * 256];
__device__ float g_dis[NN];
__device__ int   g_deg[NN];
__device__ int   g_off[NN + 1];
__device__ int   g_cur[NN];
__device__ int2  g_edge[EE];   // {src, float_bits(dis[s]*dis[d])}
// pre-rounded (tf32-representable) weights
__device__ float g_w0[128 * 128];
__device__ float g_w1[128 * 256];
__device__ float g_w2[256 * 128];

__device__ __forceinline__ uint32_t f2tf32(float x) {
    uint32_t r;
    asm("cvt.rna.tf32.f32 %0, %1;" : "=r"(r) : "f"(x));
    return r;
}
__device__ __forceinline__ float tf32r(float x) { return __uint_as_float(f2tf32(x)); }

// ---------------- fused weight rounding: 3 GEMM weight tensors -> globals ----------------
#define W0F4 (128 * 128 / 4)
#define W1F4 (128 * 256 / 4)
#define W2F4 (256 * 128 / 4)
#define WTOT (W0F4 + W1F4 + W2F4)

__global__ void round_w_kernel(
    const float* __restrict__ Wi, const float* __restrict__ W1,
    const float* __restrict__ W2) {
    int i = blockIdx.x * blockDim.x + threadIdx.x;
    if (i >= WTOT) return;
    const float4* s;
    float4* d;
    int j;
    if (i < W0F4) { s = (const float4*)Wi; d = (float4*)g_w0; j = i; }
    else if (i < W0F4 + W1F4) { s = (const float4*)W1; d = (float4*)g_w1; j = i - W0F4; }
    else { s = (const float4*)W2; d = (float4*)g_w2; j = i - W0F4 - W1F4; }
    float4 v = s[j];
    v.x = tf32r(v.x); v.y = tf32r(v.y); v.z = tf32r(v.z); v.w = tf32r(v.w);
    d[j] = v;
}

// ---------------- graph preprocessing (4 edges/thread for ATOMG MLP) ----------------
__global__ void count_deg_kernel(const int* __restrict__ dst) {
    int i = (blockIdx.x * blockDim.x + threadIdx.x) * 4;
    if (i < EE) {
        int4 d = *(const int4*)(dst + i);
        atomicAdd(&g_deg[d.x], 1);
        atomicAdd(&g_deg[d.y], 1);
        atomicAdd(&g_deg[d.z], 1);
        atomicAdd(&g_deg[d.w], 1);
    }
}

__global__ void scan_kernel() {
    __shared__ int s[1024];
    const int t = threadIdx.x;
    const int CH = (NN + 1023) / 1024;
    int start = t * CH;
    int end = min(start + CH, NN);
    int sum = 0;
    for (int i = start; i < end; i++) sum += g_deg[i];
    s[t] = sum;
    __syncthreads();
    for (int off = 1; off < 1024; off <<= 1) {
        int v = (t >= off) ? s[t - off] : 0;
        __syncthreads();
        s[t] += v;
        __syncthreads();
    }
    int run = (t == 0) ? 0 : s[t - 1];
    for (int i = start; i < end; i++) {
        g_off[i] = run;
        g_cur[i] = run;
        g_dis[i] = rsqrtf((float)(g_deg[i] + 1));
        run += g_deg[i];
    }
    if (start < NN && end == NN) g_off[NN] = run;
}

__global__ void fill_csr_kernel(const int* __restrict__ src, const int* __restrict__ dst) {
    int i = (blockIdx.x * blockDim.x + threadIdx.x) * 4;
    if (i < EE) {
        int4 s4 = *(const int4*)(src + i);
        int4 d4 = *(const int4*)(dst + i);
        int p0 = atomicAdd(&g_cur[d4.x], 1);
        int p1 = atomicAdd(&g_cur[d4.y], 1);
        int p2 = atomicAdd(&g_cur[d4.z], 1);
        int p3 = atomicAdd(&g_cur[d4.w], 1);
        g_edge[p0] = make_int2(s4.x, __float_as_int(g_dis[s4.x] * g_dis[d4.x]));
        g_edge[p1] = make_int2(s4.y, __float_as_int(g_dis[s4.y] * g_dis[d4.y]));
        g_edge[p2] = make_int2(s4.z, __float_as_int(g_dis[s4.z] * g_dis[d4.z]));
        g_edge[p3] = make_int2(s4.w, __float_as_int(g_dis[s4.w] * g_dis[d4.w]));
    }
}

// ---------------- TF32 tensor-core GEMM with cp.async pipeline (R7 champion) ----------------
// Block tile: 128 x NT. 8 warps (4 m x 2 n). K-chunk 32, 2-stage double buffering.
// Inputs must be tf32-representable, EXCEPT when CVT_A: A rounded in the load path.

#define MMA_TF32(d, a, b)                                                             \
    asm volatile(                                                                     \
        "mma.sync.aligned.m16n8k8.row.col.f32.tf32.tf32.f32 "                         \
        "{%0,%1,%2,%3}, {%4,%5,%6,%7}, {%8,%9}, {%0,%1,%2,%3};"                       \
        : "+f"((d)[0]), "+f"((d)[1]), "+f"((d)[2]), "+f"((d)[3])                      \
        : "r"((a)[0]), "r"((a)[1]), "r"((a)[2]), "r"((a)[3]), "r"((b)[0]), "r"((b)[1]))

__device__ __forceinline__ void cp_async16(uint32_t smem_addr, const void* gptr) {
    asm volatile("cp.async.cg.shared.global [%0], [%1], 16;\n" ::"r"(smem_addr), "l"(gptr));
}
__device__ __forceinline__ void cp_commit() { asm volatile("cp.async.commit_group;\n"); }
template <int W>
__device__ __forceinline__ void cp_wait() { asm volatile("cp.async.wait_group %0;\n" ::"n"(W)); }

template <int NT, bool BIAS_ACT, bool ROUND, bool CVT_A>
__global__ __launch_bounds__(256) void gemm_tc_kernel(
    const float* __restrict__ A, const float* __restrict__ B,
    const float* __restrict__ bias, float* __restrict__ C,
    int M, int N, int K) {
    constexpr int NF = NT / 16;
    constexpr int BS = NT + 4;
    constexpr int NB = NT / 32;
    __shared__ uint32_t As[2][128 * 36];
    __shared__ uint32_t Bs[2][32 * BS];

    const int tid = threadIdx.x;
    const int lane = tid & 31;
    const int wid = tid >> 5;
    const int wm = (wid & 3) * 32;
    const int wn = (wid >> 2) * (NT / 2);
    const int g = lane >> 2;
    const int t4 = lane & 3;
    const int bm = blockIdx.y * 128;
    const int bn = blockIdx.x * NT;

    const int aR = tid >> 3;
    const int aC = (tid & 7) * 4;
    const int bR = tid / (NT / 4);
    const int bC = (tid % (NT / 4)) * 4;
    constexpr int RPI = 256 / (NT / 4);

    auto issue_A = [&](int k0, int st) {
#pragma unroll
        for (int it = 0; it < 4; it++) {
            int r = it * 32 + aR;
            int gr = min(bm + r, M - 1);
            uint32_t da = (uint32_t)__cvta_generic_to_shared(&As[st][r * 36 + aC]);
            cp_async16(da, A + (size_t)gr * K + k0 + aC);
        }
    };
    auto issue_B = [&](int k0, int st) {
#pragma unroll
        for (int it = 0; it < NB; it++) {
            int r = it * RPI + bR;
            uint32_t db = (uint32_t)__cvta_generic_to_shared(&Bs[st][r * BS + bC]);
            cp_async16(db, B + (size_t)(k0 + r) * N + bn + bC);
        }
        cp_commit();
    };

    float4 ar[4];
    auto load_A_regs = [&](int k0) {
#pragma unroll
        for (int it = 0; it < 4; it++) {
            int r = it * 32 + aR;
            int gr = min(bm + r, M - 1);
            ar[it] = *(const float4*)(A + (size_t)gr * K + k0 + aC);
        }
    };
    auto sts_A_regs = [&](int st) {
#pragma unroll
        for (int it = 0; it < 4; it++) {
            int r = it * 32 + aR;
            uint32_t* p = &As[st][r * 36 + aC];
            p[0] = f2tf32(ar[it].x); p[1] = f2tf32(ar[it].y);
            p[2] = f2tf32(ar[it].z); p[3] = f2tf32(ar[it].w);
        }
    };

    float c[2][NF][4] = {};
    const int nch = K >> 5;

    if (CVT_A) load_A_regs(0); else issue_A(0, 0);
    issue_B(0, 0);

    for (int i = 0; i < nch; i++) {
        const int st = i & 1;
        if (CVT_A) sts_A_regs(st);
        if (i + 1 < nch) {
            int kn = (i + 1) << 5;
            if (!CVT_A) issue_A(kn, st ^ 1);
            issue_B(kn, st ^ 1);
            if (CVT_A) load_A_regs(kn);  // LDG overlapped with MMA below
            cp_wait<1>();
        } else {
            cp_wait<0>();
        }
        __syncthreads();

#pragma unroll
        for (int s = 0; s < 4; s++) {
            uint32_t a[2][4];
#pragma unroll
            for (int mf = 0; mf < 2; mf++) {
                int r0 = (wm + mf * 16 + g) * 36 + s * 8 + t4;
                int r1 = (wm + mf * 16 + g + 8) * 36 + s * 8 + t4;
                a[mf][0] = As[st][r0];
                a[mf][1] = As[st][r1];
                a[mf][2] = As[st][r0 + 4];
                a[mf][3] = As[st][r1 + 4];
            }
            uint32_t b[NF][2];
#pragma unroll
            for (int nf = 0; nf < NF; nf++) {
                int col = wn + nf * 8 + g;
                b[nf][0] = Bs[st][(s * 8 + t4) * BS + col];
                b[nf][1] = Bs[st][(s * 8 + t4 + 4) * BS + col];
            }
#pragma unroll
            for (int mf = 0; mf < 2; mf++)
#pragma unroll
                for (int nf = 0; nf < NF; nf++) MMA_TF32(c[mf][nf], a[mf], b[nf]);
        }
        __syncthreads();
    }

#pragma unroll
    for (int mf = 0; mf < 2; mf++) {
        int r0 = bm + wm + mf * 16 + g;
        int r1 = r0 + 8;
#pragma unroll
        for (int nf = 0; nf < NF; nf++) {
            int col = bn + wn + nf * 8 + 2 * t4;
            float v0 = c[mf][nf][0], v1 = c[mf][nf][1];
            float v2 = c[mf][nf][2], v3 = c[mf][nf][3];
            if (BIAS_ACT) {
                float bb0 = bias[col], bb1 = bias[col + 1];
                v0 += bb0; v1 += bb1; v2 += bb0; v3 += bb1;
                v0 = v0 > 0.f ? v0 : 0.01f * v0;
                v1 = v1 > 0.f ? v1 : 0.01f * v1;
                v2 = v2 > 0.f ? v2 : 0.01f * v2;
                v3 = v3 > 0.f ? v3 : 0.01f * v3;
            }
            if (ROUND) {
                v0 = tf32r(v0); v1 = tf32r(v1); v2 = tf32r(v2); v3 = tf32r(v3);
            }
            if (r0 < M) { float2 o; o.x = v0; o.y = v1; *(float2*)(C + (size_t)r0 * N + col) = o; }
            if (r1 < M) { float2 o; o.x = v2; o.y = v3; *(float2*)(C + (size_t)r1 * N + col) = o; }
        }
    }
}

// ---------------- gather aggregation: H = [lrelu](S·Y [+ b]) ----------------
// One warp per node, packed edges, 8-deep gather batching (R7 champion).
template <int C, bool BIAS_ACT, bool ROUND>
__global__ __launch_bounds__(256) void agg_kernel(
    const float* __restrict__ Y, const float* __restrict__ bias, float* __restrict__ H) {
    int node = (blockIdx.x * blockDim.x + threadIdx.x) >> 5;
    int lane = threadIdx.x & 31;
    if (node >= NN) return;

    float dn = g_dis[node];
    float selfw = dn * dn;
    int beg = g_off[node];
    int end = g_off[node + 1];

    float4 acc;
    {
        float4 u = ((const float4*)(Y + (size_t)node * C))[lane];
        acc.x = selfw * u.x; acc.y = selfw * u.y;
        acc.z = selfw * u.z; acc.w = selfw * u.w;
    }
    int i = beg;
    for (; i + 8 <= end; i += 8) {
        int2 e[8];
#pragma unroll
        for (int j = 0; j < 8; j++) e[j] = g_edge[i + j];
        float4 u[8];
#pragma unroll
        for (int j = 0; j < 8; j++) u[j] = ((const float4*)(Y + (size_t)e[j].x * C))[lane];
#pragma unroll
        for (int j = 0; j < 8; j++) {
            float w = __int_as_float(e[j].y);
            acc.x += w * u[j].x;
            acc.y += w * u[j].y;
            acc.z += w * u[j].z;
            acc.w += w * u[j].w;
        }
    }
    for (; i < end; i++) {
        int2 e = g_edge[i];
        float w = __int_as_float(e.y);
        float4 u = ((const float4*)(Y + (size_t)e.x * C))[lane];
        acc.x += w * u.x;
        acc.y += w * u.y;
        acc.z += w * u.z;
        acc.w += w * u.w;
    }
    if (BIAS_ACT) {
        float4 b = ((const float4*)bias)[lane];
        acc.x += b.x; acc.y += b.y; acc.z += b.z; acc.w += b.w;
        acc.x = acc.x > 0.f ? acc.x : 0.01f * acc.x;
        acc.y = acc.y > 0.f ? acc.y : 0.01f * acc.y;
        acc.z = acc.z > 0.f ? acc.z : 0.01f * acc.z;
        acc.w = acc.w > 0.f ? acc.w : 0.01f * acc.w;
    }
    if (ROUND) {
        acc.x = tf32r(acc.x); acc.y = tf32r(acc.y);
        acc.z = tf32r(acc.z); acc.w = tf32r(acc.w);
    }
    ((float4*)(H + (size_t)node * C))[lane] = acc;
}

// ---------------- agg2 fused with gemm3: Y3 = lrelu(S·Y2 + b2) @ W3 ----------------
// Per warp: compute h2 row (128 ch) as in agg_kernel<128,true,false>, stage to
// per-warp smem strip, then fp32 matvec with raw W3 [128x64]. No block barrier.
__global__ __launch_bounds__(256) void agg2_gemm3_kernel(
    const float* __restrict__ Y, const float* __restrict__ bias,
    const float* __restrict__ W3, float* __restrict__ Y3) {
    __shared__ float sh[8][128];
    int node = (blockIdx.x * blockDim.x + threadIdx.x) >> 5;
    int lane = threadIdx.x & 31;
    int warp = (threadIdx.x >> 5);
    if (node >= NN) return;

    float dn = g_dis[node];
    float selfw = dn * dn;
    int beg = g_off[node];
    int end = g_off[node + 1];

    float4 acc;
    {
        float4 u = ((const float4*)(Y + (size_t)node * 128))[lane];
        acc.x = selfw * u.x; acc.y = selfw * u.y;
        acc.z = selfw * u.z; acc.w = selfw * u.w;
    }
    int i = beg;
    for (; i + 8 <= end; i += 8) {
        int2 e[8];
#pragma unroll
        for (int j = 0; j < 8; j++) e[j] = g_edge[i + j];
        float4 u[8];
#pragma unroll
        for (int j = 0; j < 8; j++) u[j] = ((const float4*)(Y + (size_t)e[j].x * 128))[lane];
#pragma unroll
        for (int j = 0; j < 8; j++) {
            float w = __int_as_float(e[j].y);
            acc.x += w * u[j].x;
            acc.y += w * u[j].y;
            acc.z += w * u[j].z;
            acc.w += w * u[j].w;
        }
    }
    for (; i < end; i++) {
        int2 e = g_edge[i];
        float w = __int_as_float(e.y);
        float4 u = ((const float4*)(Y + (size_t)e.x * 128))[lane];
        acc.x += w * u.x;
        acc.y += w * u.y;
        acc.z += w * u.z;
        acc.w += w * u.w;
    }
    {
        float4 b = ((const float4*)bias)[lane];
        acc.x += b.x; acc.y += b.y; acc.z += b.z; acc.w += b.w;
        acc.x = acc.x > 0.f ? acc.x : 0.01f * acc.x;
        acc.y = acc.y > 0.f ? acc.y : 0.01f * acc.y;
        acc.z = acc.z > 0.f ? acc.z : 0.01f * acc.z;
        acc.w = acc.w > 0.f ? acc.w : 0.01f * acc.w;
    }

    // stage h2 row to this warp's smem strip
    *(float4*)(&sh[warp][lane * 4]) = acc;
    __syncwarp();

    // matvec: Y3[node][2*lane + {0,1}] = sum_k h2[k] * W3[k][2*lane + {0,1}]
    float o0 = 0.f, o1 = 0.f;
#pragma unroll 4
    for (int k = 0; k < 128; k++) {
        float s = sh[warp][k];                       // broadcast LDS
        float2 w = ((const float2*)W3)[k * 32 + lane];  // L1-resident
        o0 += s * w.x;
        o1 += s * w.y;
    }
    float2 o;
    o.x = o0;
    o.y = o1;
    ((float2*)(Y3 + (size_t)node * 64))[lane] = o;
}

// ---------------- final agg (C=64) fused with output projection; 16-edge batches ----------------
__global__ __launch_bounds__(256) void agg64_out_kernel(
    const float* __restrict__ Y, const float* __restrict__ bias,
    const float* __restrict__ Wout, const float* __restrict__ bout,
    float* __restrict__ out) {
    int node = (blockIdx.x * blockDim.x + threadIdx.x) >> 5;
    int lane = threadIdx.x & 31;
    if (node >= NN) return;

    float dn = g_dis[node];
    float selfw = dn * dn;
    int beg = g_off[node];
    int end = g_off[node + 1];

    float2 acc;
    {
        float2 u = ((const float2*)(Y + (size_t)node * 64))[lane];
        acc.x = selfw * u.x;
        acc.y = selfw * u.y;
    }
    int i = beg;
    for (; i + 16 <= end; i += 16) {
        int2 e[16];
#pragma unroll
        for (int j = 0; j < 16; j++) e[j] = g_edge[i + j];
        float2 u[16];
#pragma unroll
        for (int j = 0; j < 16; j++) u[j] = ((const float2*)(Y + (size_t)e[j].x * 64))[lane];
#pragma unroll
        for (int j = 0; j < 16; j++) {
            float w = __int_as_float(e[j].y);
            acc.x += w * u[j].x;
            acc.y += w * u[j].y;
        }
    }
    for (; i < end; i++) {
        int2 e = g_edge[i];
        float w = __int_as_float(e.y);
        float2 u = ((const float2*)(Y + (size_t)e.x * 64))[lane];
        acc.x += w * u.x;
        acc.y += w * u.y;
    }
    float2 b = ((const float2*)bias)[lane];
    acc.x += b.x; acc.y += b.y;
    acc.x = acc.x > 0.f ? acc.x : 0.01f * acc.x;
    acc.y = acc.y > 0.f ? acc.y : 0.01f * acc.y;

    float2 w = ((const float2*)Wout)[lane];
    float v = acc.x * w.x + acc.y * w.y;
#pragma unroll
    for (int o = 16; o > 0; o >>= 1) v += __shfl_down_sync(0xffffffffu, v, o);
    if (lane == 0) out[node] = v + bout[0];
}

// ---------------- launch (champion schedule; gemm3 fused into agg2) ----------------
extern "C" void kernel_launch(void* const* d_in, const int* in_sizes, int n_in,
                              void* d_out, int out_size) {
    const float* x    = (const float*)d_in[0];
    const int*   ei   = (const int*)d_in[1];
    const float* W_in = (const float*)d_in[2];
    const float* b_in = (const float*)d_in[3];
    const float* W1   = (const float*)d_in[4];
    const float* b1   = (const float*)d_in[5];
    const float* W2   = (const float*)d_in[6];
    const float* b2   = (const float*)d_in[7];
    const float* W3   = (const float*)d_in[8];
    const float* b3   = (const float*)d_in[9];
    const float* Wo   = (const float*)d_in[10];
    const float* bo   = (const float*)d_in[11];
    float* out = (float*)d_out;

    const int* src = ei;
    const int* dst = ei + EE;

    float *buf0, *buf1, *w0, *w1, *w2;
    cudaGetSymbolAddress((void**)&buf0, g_buf0);
    cudaGetSymbolAddress((void**)&buf1, g_buf1);
    cudaGetSymbolAddress((void**)&w0, g_w0);
    cudaGetSymbolAddress((void**)&w1, g_w1);
    cudaGetSymbolAddress((void**)&w2, g_w2);
    int* degp;
    cudaGetSymbolAddress((void**)&degp, g_deg);

    static cudaStream_t s2 = nullptr;
    static cudaEvent_t ev_fork = nullptr, ev_join = nullptr;
    if (s2 == nullptr) {
        cudaStreamCreateWithFlags(&s2, cudaStreamNonBlocking);
        cudaEventCreateWithFlags(&ev_fork, cudaEventDisableTiming);
        cudaEventCreateWithFlags(&ev_join, cudaEventDisableTiming);
    }

    // ---- fork: graph preprocessing on s2, concurrent with round_w+gemm0 on main ----
    cudaEventRecord(ev_fork, 0);
    cudaStreamWaitEvent(s2, ev_fork, 0);

    cudaMemsetAsync(degp, 0, NN * sizeof(int), s2);
    count_deg_kernel<<<(EE / 4 + 255) / 256, 256, 0, s2>>>(dst);
    scan_kernel<<<1, 1024, 0, s2>>>();
    fill_csr_kernel<<<(EE / 4 + 255) / 256, 256, 0, s2>>>(src, dst);
    cudaEventRecord(ev_join, s2);

    // main stream: round GEMM weights (W_in/W1/W2), then gemm0
    round_w_kernel<<<(WTOT + 255) / 256, 256>>>(W_in, W1, W2);

    const int MT = (NN + 127) / 128;
    const int AGG_GRID = (NN + 7) / 8;

    // h0 = lrelu(x @ W_in + b_in), rounded                 [N,128]
    gemm_tc_kernel<128, true, true, true><<<dim3(1, MT), 256>>>(x, w0, b_in, buf0, NN, 128, 128);

    // ---- join: CSR ready before the first aggregation ----
    cudaStreamWaitEvent(0, ev_join, 0);

    // layer 1 (agg first: S·(h@W1) == (S·h)@W1):
    agg_kernel<128, false, true><<<AGG_GRID, 256>>>(buf0, nullptr, buf1);   // Z1 = S·h0, rounded
    gemm_tc_kernel<128, true, true, false><<<dim3(2, MT), 256>>>(buf1, w1, b1, buf0, NN, 256, 128);  // h1
    // layer 2 (gemm first):
    gemm_tc_kernel<128, false, false, false><<<dim3(1, MT), 256>>>(buf0, w2, nullptr, buf1, NN, 128, 256);  // Y2
    // layer 3 fused: h2 = lrelu(S·Y2 + b2); Y3 = h2 @ W3 (fp32, raw W3)
    agg2_gemm3_kernel<<<AGG_GRID, 256>>>(buf1, b2, W3, buf0);               // Y3 -> buf0
    // h3 = lrelu(S·Y3 + b3); out = h3 @ W_out + b_out  (fused)
    agg64_out_kernel<<<AGG_GRID, 256>>>(buf0, b3, Wo, bo, out);
}

// round 17
// speedup vs baseline: 1.1657x; 1.1657x over previous
#include <cuda_runtime.h>
#include <cstdint>

#define NN 50000
#define EE 800000
#define HALF 25088   // 196*128; multiple of 128 (gemm tiles) and 8 (agg blocks)

// ---------------- scratch (static device globals; no allocation) ----------------
__device__ float g_buf0[NN * 256];
__device__ float g_buf1[NN * 256];
__device__ float g_dis[NN];
__device__ int   g_deg[NN];
__device__ int   g_off[NN + 1];
__device__ int   g_cur[NN];
__device__ int2  g_edge[EE];   // {src, float_bits(dis[s]*dis[d])}
// pre-rounded (tf32-representable) weights
__device__ float g_w0[128 * 128];
__device__ float g_w1[128 * 256];
__device__ float g_w2[256 * 128];
__device__ float g_w3[128 * 64];

__device__ __forceinline__ uint32_t f2tf32(float x) {
    uint32_t r;
    asm("cvt.rna.tf32.f32 %0, %1;" : "=r"(r) : "f"(x));
    return r;
}
__device__ __forceinline__ float tf32r(float x) { return __uint_as_float(f2tf32(x)); }

// ---------------- fused weight rounding: 4 weight tensors -> globals ----------------
#define W0F4 (128 * 128 / 4)
#define W1F4 (128 * 256 / 4)
#define W2F4 (256 * 128 / 4)
#define W3F4 (128 * 64 / 4)
#define WTOT (W0F4 + W1F4 + W2F4 + W3F4)

__global__ void round_w_kernel(
    const float* __restrict__ Wi, const float* __restrict__ W1,
    const float* __restrict__ W2, const float* __restrict__ W3) {
    int i = blockIdx.x * blockDim.x + threadIdx.x;
    if (i >= WTOT) return;
    const float4* s;
    float4* d;
    int j;
    if (i < W0F4) { s = (const float4*)Wi; d = (float4*)g_w0; j = i; }
    else if (i < W0F4 + W1F4) { s = (const float4*)W1; d = (float4*)g_w1; j = i - W0F4; }
    else if (i < W0F4 + W1F4 + W2F4) { s = (const float4*)W2; d = (float4*)g_w2; j = i - W0F4 - W1F4; }
    else { s = (const float4*)W3; d = (float4*)g_w3; j = i - W0F4 - W1F4 - W2F4; }
    float4 v = s[j];
    v.x = tf32r(v.x); v.y = tf32r(v.y); v.z = tf32r(v.z); v.w = tf32r(v.w);
    d[j] = v;
}

// ---------------- graph preprocessing (4 edges/thread for ATOMG MLP) ----------------
__global__ void count_deg_kernel(const int* __restrict__ dst) {
    int i = (blockIdx.x * blockDim.x + threadIdx.x) * 4;
    if (i < EE) {
        int4 d = *(const int4*)(dst + i);
        atomicAdd(&g_deg[d.x], 1);
        atomicAdd(&g_deg[d.y], 1);
        atomicAdd(&g_deg[d.z], 1);
        atomicAdd(&g_deg[d.w], 1);
    }
}

__global__ void scan_kernel() {
    __shared__ int s[1024];
    const int t = threadIdx.x;
    const int CH = (NN + 1023) / 1024;
    int start = t * CH;
    int end = min(start + CH, NN);
    int sum = 0;
    for (int i = start; i < end; i++) sum += g_deg[i];
    s[t] = sum;
    __syncthreads();
    for (int off = 1; off < 1024; off <<= 1) {
        int v = (t >= off) ? s[t - off] : 0;
        __syncthreads();
        s[t] += v;
        __syncthreads();
    }
    int run = (t == 0) ? 0 : s[t - 1];
    for (int i = start; i < end; i++) {
        g_off[i] = run;
        g_cur[i] = run;
        g_dis[i] = rsqrtf((float)(g_deg[i] + 1));
        run += g_deg[i];
    }
    if (start < NN && end == NN) g_off[NN] = run;
}

__global__ void fill_csr_kernel(const int* __restrict__ src, const int* __restrict__ dst) {
    int i = (blockIdx.x * blockDim.x + threadIdx.x) * 4;
    if (i < EE) {
        int4 s4 = *(const int4*)(src + i);
        int4 d4 = *(const int4*)(dst + i);
        int p0 = atomicAdd(&g_cur[d4.x], 1);
        int p1 = atomicAdd(&g_cur[d4.y], 1);
        int p2 = atomicAdd(&g_cur[d4.z], 1);
        int p3 = atomicAdd(&g_cur[d4.w], 1);
        g_edge[p0] = make_int2(s4.x, __float_as_int(g_dis[s4.x] * g_dis[d4.x]));
        g_edge[p1] = make_int2(s4.y, __float_as_int(g_dis[s4.y] * g_dis[d4.y]));
        g_edge[p2] = make_int2(s4.z, __float_as_int(g_dis[s4.z] * g_dis[d4.z]));
        g_edge[p3] = make_int2(s4.w, __float_as_int(g_dis[s4.w] * g_dis[d4.w]));
    }
}

// ---------------- TF32 tensor-core GEMM with cp.async pipeline (R7 champion) ----------------
// Block tile: 128 x NT. 8 warps (4 m x 2 n). K-chunk 32, 2-stage double buffering.
// Operates on an M-row slice; caller offsets A and C base pointers for half-chains.

#define MMA_TF32(d, a, b)                                                             \
    asm volatile(                                                                     \
        "mma.sync.aligned.m16n8k8.row.col.f32.tf32.tf32.f32 "                         \
        "{%0,%1,%2,%3}, {%4,%5,%6,%7}, {%8,%9}, {%0,%1,%2,%3};"                       \
        : "+f"((d)[0]), "+f"((d)[1]), "+f"((d)[2]), "+f"((d)[3])                      \
        : "r"((a)[0]), "r"((a)[1]), "r"((a)[2]), "r"((a)[3]), "r"((b)[0]), "r"((b)[1]))

__device__ __forceinline__ void cp_async16(uint32_t smem_addr, const void* gptr) {
    asm volatile("cp.async.cg.shared.global [%0], [%1], 16;\n" ::"r"(smem_addr), "l"(gptr));
}
__device__ __forceinline__ void cp_commit() { asm volatile("cp.async.commit_group;\n"); }
template <int W>
__device__ __forceinline__ void cp_wait() { asm volatile("cp.async.wait_group %0;\n" ::"n"(W)); }

template <int NT, bool BIAS_ACT, bool ROUND, bool CVT_A>
__global__ __launch_bounds__(256) void gemm_tc_kernel(
    const float* __restrict__ A, const float* __restrict__ B,
    const float* __restrict__ bias, float* __restrict__ C,
    int M, int N, int K) {
    constexpr int NF = NT / 16;
    constexpr int BS = NT + 4;
    constexpr int NB = NT / 32;
    __shared__ uint32_t As[2][128 * 36];
    __shared__ uint32_t Bs[2][32 * BS];

    const int tid = threadIdx.x;
    const int lane = tid & 31;
    const int wid = tid >> 5;
    const int wm = (wid & 3) * 32;
    const int wn = (wid >> 2) * (NT / 2);
    const int g = lane >> 2;
    const int t4 = lane & 3;
    const int bm = blockIdx.y * 128;
    const int bn = blockIdx.x * NT;

    const int aR = tid >> 3;
    const int aC = (tid & 7) * 4;
    const int bR = tid / (NT / 4);
    const int bC = (tid % (NT / 4)) * 4;
    constexpr int RPI = 256 / (NT / 4);

    auto issue_A = [&](int k0, int st) {
#pragma unroll
        for (int it = 0; it < 4; it++) {
            int r = it * 32 + aR;
            int gr = min(bm + r, M - 1);
            uint32_t da = (uint32_t)__cvta_generic_to_shared(&As[st][r * 36 + aC]);
            cp_async16(da, A + (size_t)gr * K + k0 + aC);
        }
    };
    auto issue_B = [&](int k0, int st) {
#pragma unroll
        for (int it = 0; it < NB; it++) {
            int r = it * RPI + bR;
            uint32_t db = (uint32_t)__cvta_generic_to_shared(&Bs[st][r * BS + bC]);
            cp_async16(db, B + (size_t)(k0 + r) * N + bn + bC);
        }
        cp_commit();
    };

    float4 ar[4];
    auto load_A_regs = [&](int k0) {
#pragma unroll
        for (int it = 0; it < 4; it++) {
            int r = it * 32 + aR;
            int gr = min(bm + r, M - 1);
            ar[it] = *(const float4*)(A + (size_t)gr * K + k0 + aC);
        }
    };
    auto sts_A_regs = [&](int st) {
#pragma unroll
        for (int it = 0; it < 4; it++) {
            int r = it * 32 + aR;
            uint32_t* p = &As[st][r * 36 + aC];
            p[0] = f2tf32(ar[it].x); p[1] = f2tf32(ar[it].y);
            p[2] = f2tf32(ar[it].z); p[3] = f2tf32(ar[it].w);
        }
    };

    float c[2][NF][4] = {};
    const int nch = K >> 5;

    if (CVT_A) load_A_regs(0); else issue_A(0, 0);
    issue_B(0, 0);

    for (int i = 0; i < nch; i++) {
        const int st = i & 1;
        if (CVT_A) sts_A_regs(st);
        if (i + 1 < nch) {
            int kn = (i + 1) << 5;
            if (!CVT_A) issue_A(kn, st ^ 1);
            issue_B(kn, st ^ 1);
            if (CVT_A) load_A_regs(kn);  // LDG overlapped with MMA below
            cp_wait<1>();
        } else {
            cp_wait<0>();
        }
        __syncthreads();

#pragma unroll
        for (int s = 0; s < 4; s++) {
            uint32_t a[2][4];
#pragma unroll
            for (int mf = 0; mf < 2; mf++) {
                int r0 = (wm + mf * 16 + g) * 36 + s * 8 + t4;
                int r1 = (wm + mf * 16 + g + 8) * 36 + s * 8 + t4;
                a[mf][0] = As[st][r0];
                a[mf][1] = As[st][r1];
                a[mf][2] = As[st][r0 + 4];
                a[mf][3] = As[st][r1 + 4];
            }
            uint32_t b[NF][2];
#pragma unroll
            for (int nf = 0; nf < NF; nf++) {
                int col = wn + nf * 8 + g;
                b[nf][0] = Bs[st][(s * 8 + t4) * BS + col];
                b[nf][1] = Bs[st][(s * 8 + t4 + 4) * BS + col];
            }
#pragma unroll
            for (int mf = 0; mf < 2; mf++)
#pragma unroll
                for (int nf = 0; nf < NF; nf++) MMA_TF32(c[mf][nf], a[mf], b[nf]);
        }
        __syncthreads();
    }

#pragma unroll
    for (int mf = 0; mf < 2; mf++) {
        int r0 = bm + wm + mf * 16 + g;
        int r1 = r0 + 8;
#pragma unroll
        for (int nf = 0; nf < NF; nf++) {
            int col = bn + wn + nf * 8 + 2 * t4;
            float v0 = c[mf][nf][0], v1 = c[mf][nf][1];
            float v2 = c[mf][nf][2], v3 = c[mf][nf][3];
            if (BIAS_ACT) {
                float bb0 = bias[col], bb1 = bias[col + 1];
                v0 += bb0; v1 += bb1; v2 += bb0; v3 += bb1;
                v0 = v0 > 0.f ? v0 : 0.01f * v0;
                v1 = v1 > 0.f ? v1 : 0.01f * v1;
                v2 = v2 > 0.f ? v2 : 0.01f * v2;
                v3 = v3 > 0.f ? v3 : 0.01f * v3;
            }
            if (ROUND) {
                v0 = tf32r(v0); v1 = tf32r(v1); v2 = tf32r(v2); v3 = tf32r(v3);
            }
            if (r0 < M) { float2 o; o.x = v0; o.y = v1; *(float2*)(C + (size_t)r0 * N + col) = o; }
            if (r1 < M) { float2 o; o.x = v2; o.y = v3; *(float2*)(C + (size_t)r1 * N + col) = o; }
        }
    }
}

// ---------------- gather aggregation over node range [node0, node1) ----------------
// One warp per node, packed edges, 8-deep gather batching (R7 champion math).
template <int C, bool BIAS_ACT, bool ROUND>
__global__ __launch_bounds__(256) void agg_kernel(
    const float* __restrict__ Y, const float* __restrict__ bias, float* __restrict__ H,
    int node0, int node1) {
    int node = node0 + ((blockIdx.x * blockDim.x + threadIdx.x) >> 5);
    int lane = threadIdx.x & 31;
    if (node >= node1) return;

    float dn = g_dis[node];
    float selfw = dn * dn;
    int beg = g_off[node];
    int end = g_off[node + 1];

    float4 acc;
    {
        float4 u = ((const float4*)(Y + (size_t)node * C))[lane];
        acc.x = selfw * u.x; acc.y = selfw * u.y;
        acc.z = selfw * u.z; acc.w = selfw * u.w;
    }
    int i = beg;
    for (; i + 8 <= end; i += 8) {
        int2 e[8];
#pragma unroll
        for (int j = 0; j < 8; j++) e[j] = g_edge[i + j];
        float4 u[8];
#pragma unroll
        for (int j = 0; j < 8; j++) u[j] = ((const float4*)(Y + (size_t)e[j].x * C))[lane];
#pragma unroll
        for (int j = 0; j < 8; j++) {
            float w = __int_as_float(e[j].y);
            acc.x += w * u[j].x;
            acc.y += w * u[j].y;
            acc.z += w * u[j].z;
            acc.w += w * u[j].w;
        }
    }
    for (; i < end; i++) {
        int2 e = g_edge[i];
        float w = __int_as_float(e.y);
        float4 u = ((const float4*)(Y + (size_t)e.x * C))[lane];
        acc.x += w * u.x;
        acc.y += w * u.y;
        acc.z += w * u.z;
        acc.w += w * u.w;
    }
    if (BIAS_ACT) {
        float4 b = ((const float4*)bias)[lane];
        acc.x += b.x; acc.y += b.y; acc.z += b.z; acc.w += b.w;
        acc.x = acc.x > 0.f ? acc.x : 0.01f * acc.x;
        acc.y = acc.y > 0.f ? acc.y : 0.01f * acc.y;
        acc.z = acc.z > 0.f ? acc.z : 0.01f * acc.z;
        acc.w = acc.w > 0.f ? acc.w : 0.01f * acc.w;
    }
    if (ROUND) {
        acc.x = tf32r(acc.x); acc.y = tf32r(acc.y);
        acc.z = tf32r(acc.z); acc.w = tf32r(acc.w);
    }
    ((float4*)(H + (size_t)node * C))[lane] = acc;
}

// ---------------- final agg (C=64) fused with output projection; 16-edge batches ----------------
__global__ __launch_bounds__(256) void agg64_out_kernel(
    const float* __restrict__ Y, const float* __restrict__ bias,
    const float* __restrict__ Wout, const float* __restrict__ bout,
    float* __restrict__ out) {
    int node = (blockIdx.x * blockDim.x + threadIdx.x) >> 5;
    int lane = threadIdx.x & 31;
    if (node >= NN) return;

    float dn = g_dis[node];
    float selfw = dn * dn;
    int beg = g_off[node];
    int end = g_off[node + 1];

    float2 acc;
    {
        float2 u = ((const float2*)(Y + (size_t)node * 64))[lane];
        acc.x = selfw * u.x;
        acc.y = selfw * u.y;
    }
    int i = beg;
    for (; i + 16 <= end; i += 16) {
        int2 e[16];
#pragma unroll
        for (int j = 0; j < 16; j++) e[j] = g_edge[i + j];
        float2 u[16];
#pragma unroll
        for (int j = 0; j < 16; j++) u[j] = ((const float2*)(Y + (size_t)e[j].x * 64))[lane];
#pragma unroll
        for (int j = 0; j < 16; j++) {
            float w = __int_as_float(e[j].y);
            acc.x += w * u[j].x;
            acc.y += w * u[j].y;
        }
    }
    for (; i < end; i++) {
        int2 e = g_edge[i];
        float w = __int_as_float(e.y);
        float2 u = ((const float2*)(Y + (size_t)e.x * 64))[lane];
        acc.x += w * u.x;
        acc.y += w * u.y;
    }
    float2 b = ((const float2*)bias)[lane];
    acc.x += b.x; acc.y += b.y;
    acc.x = acc.x > 0.f ? acc.x : 0.01f * acc.x;
    acc.y = acc.y > 0.f ? acc.y : 0.01f * acc.y;

    float2 w = ((const float2*)Wout)[lane];
    float v = acc.x * w.x + acc.y * w.y;
#pragma unroll
    for (int o = 16; o > 0; o >>= 1) v += __shfl_down_sync(0xffffffffu, v, o);
    if (lane == 0) out[node] = v + bout[0];
}

// ---------------- launch: champion kernels, half-chain pipelining ----------------
extern "C" void kernel_launch(void* const* d_in, const int* in_sizes, int n_in,
                              void* d_out, int out_size) {
    const float* x    = (const float*)d_in[0];
    const int*   ei   = (const int*)d_in[1];
    const float* W_in = (const float*)d_in[2];
    const float* b_in = (const float*)d_in[3];
    const float* W1   = (const float*)d_in[4];
    const float* b1   = (const float*)d_in[5];
    const float* W2   = (const float*)d_in[6];
    const float* b2   = (const float*)d_in[7];
    const float* W3   = (const float*)d_in[8];
    const float* b3   = (const float*)d_in[9];
    const float* Wo   = (const float*)d_in[10];
    const float* bo   = (const float*)d_in[11];
    float* out = (float*)d_out;

    const int* src = ei;
    const int* dst = ei + EE;

    float *buf0, *buf1, *w0, *w1, *w2, *w3;
    cudaGetSymbolAddress((void**)&buf0, g_buf0);
    cudaGetSymbolAddress((void**)&buf1, g_buf1);
    cudaGetSymbolAddress((void**)&w0, g_w0);
    cudaGetSymbolAddress((void**)&w1, g_w1);
    cudaGetSymbolAddress((void**)&w2, g_w2);
    cudaGetSymbolAddress((void**)&w3, g_w3);
    int* degp;
    cudaGetSymbolAddress((void**)&degp, g_deg);

    static cudaStream_t s2 = nullptr, s3 = nullptr;
    static cudaEvent_t ev_fork = nullptr, ev_csr = nullptr, ev_g0 = nullptr;
    static cudaEvent_t ev_a2 = nullptr, ev_b2 = nullptr, ev_b3 = nullptr;
    if (s2 == nullptr) {
        cudaStreamCreateWithFlags(&s2, cudaStreamNonBlocking);
        cudaStreamCreateWithFlags(&s3, cudaStreamNonBlocking);
        cudaEventCreateWithFlags(&ev_fork, cudaEventDisableTiming);
        cudaEventCreateWithFlags(&ev_csr, cudaEventDisableTiming);
        cudaEventCreateWithFlags(&ev_g0, cudaEventDisableTiming);
        cudaEventCreateWithFlags(&ev_a2, cudaEventDisableTiming);
        cudaEventCreateWithFlags(&ev_b2, cudaEventDisableTiming);
        cudaEventCreateWithFlags(&ev_b3, cudaEventDisableTiming);
    }

    // half-chain geometry
    const int MT_A = HALF / 128;                    // 196 tiles, rows [0, HALF)
    const int CNT_B = NN - HALF;                    // 24912 rows
    const int MT_B = (CNT_B + 127) / 128;           // 195 tiles
    const int AGG_A = HALF / 8;                     // 3136 blocks
    const int AGG_B = (CNT_B + 7) / 8;              // 3114 blocks
    const int AGG_FULL = (NN + 7) / 8;

    // ---- fork: graph preprocessing on s2, concurrent with round_w+gemm0 on main ----
    cudaEventRecord(ev_fork, 0);
    cudaStreamWaitEvent(s2, ev_fork, 0);

    cudaMemsetAsync(degp, 0, NN * sizeof(int), s2);
    count_deg_kernel<<<(EE / 4 + 255) / 256, 256, 0, s2>>>(dst);
    scan_kernel<<<1, 1024, 0, s2>>>();
    fill_csr_kernel<<<(EE / 4 + 255) / 256, 256, 0, s2>>>(src, dst);
    cudaEventRecord(ev_csr, s2);

    // main stream: round all weights, then gemm0 (x rounded in its A-load path)
    round_w_kernel<<<(WTOT + 255) / 256, 256>>>(W_in, W1, W2, W3);
    const int MT_FULL = (NN + 127) / 128;
    gemm_tc_kernel<128, true, true, true><<<dim3(1, MT_FULL), 256>>>(x, w0, b_in, buf0, NN, 128, 128);
    cudaEventRecord(ev_g0, 0);

    // ---- half-chain A (rows/nodes [0, HALF)) on main ----
    cudaStreamWaitEvent(0, ev_csr, 0);
    agg_kernel<128, false, true><<<AGG_A, 256>>>(buf0, nullptr, buf1, 0, HALF);                    // Z1[0:H)
    gemm_tc_kernel<128, true, true, false><<<dim3(2, MT_A), 256>>>(buf1, w1, b1, buf0, HALF, 256, 128);   // h1[0:H)
    gemm_tc_kernel<128, false, false, false><<<dim3(1, MT_A), 256>>>(buf0, w2, nullptr, buf1, HALF, 128, 256); // Y2[0:H)
    cudaEventRecord(ev_a2, 0);

    // ---- half-chain B (rows/nodes [HALF, NN)) on s3 ----
    cudaStreamWaitEvent(s3, ev_g0, 0);
    cudaStreamWaitEvent(s3, ev_csr, 0);
    agg_kernel<128, false, true><<<AGG_B, 256, 0, s3>>>(buf0, nullptr, buf1, HALF, NN);            // Z1[H:N)
    gemm_tc_kernel<128, true, true, false><<<dim3(2, MT_B), 256, 0, s3>>>(
        buf1 + (size_t)HALF * 128, w1, b1, buf0 + (size_t)HALF * 256, CNT_B, 256, 128);            // h1[H:N)
    gemm_tc_kernel<128, false, false, false><<<dim3(1, MT_B), 256, 0, s3>>>(
        buf0 + (size_t)HALF * 256, w2, nullptr, buf1 + (size_t)HALF * 128, CNT_B, 128, 256);       // Y2[H:N)
    cudaEventRecord(ev_b2, s3);

    // ---- layer 3: agg2 halves (scattered read of full Y2 -> cross-join), gemm3 halves ----
    cudaStreamWaitEvent(0, ev_b2, 0);   // main needs Y2[H:N)
    agg_kernel<128, true, true><<<AGG_A, 256>>>(buf1, b2, buf0, 0, HALF);                          // h2[0:H)
    gemm_tc_kernel<64, false, false, false><<<dim3(1, MT_A), 256>>>(buf0, w3, nullptr, buf1, HALF, 64, 128);   // Y3[0:H)

    cudaStreamWaitEvent(s3, ev_a2, 0);  // s3 needs Y2[0:H)
    agg_kernel<128, true, true><<<AGG_B, 256, 0, s3>>>(buf1, b2, buf0, HALF, NN);                  // h2[H:N)
    gemm_tc_kernel<64, false, false, false><<<dim3(1, MT_B), 256, 0, s3>>>(
        buf0 + (size_t)HALF * 128, w3, nullptr, buf1 + (size_t)HALF * 64, CNT_B, 64, 128);         // Y3[H:N)
    cudaEventRecord(ev_b3, s3);

    // ---- final: agg64_out reads full Y3 ----
    cudaStreamWaitEvent(0, ev_b3, 0);
    agg64_out_kernel<<<AGG_FULL, 256>>>(buf1, b3, Wo, bo, out);
}